// round 12
// baseline (speedup 1.0000x reference)
#include <cuda_runtime.h>
#include <cuda_bf16.h>
#include <math.h>
#include <stdint.h>

// Problem dims (fixed by the reference)
#define B_   4
#define S_   2048
#define E_   512
#define H_   8
#define DH_  64
#define FF2  2048
#define M_   8192   // B_*S_

// ---------------------------------------------------------------------------
// Scratch buffers (device globals -- no allocations allowed)
// ---------------------------------------------------------------------------
static __device__ __nv_bfloat16 g_nb  [(size_t)M_ * E_];   // LN1 out
static __device__ __nv_bfloat16 g_qb  [(size_t)M_ * E_];   // [B,H,S,DH]
static __device__ __nv_bfloat16 g_kb  [(size_t)M_ * E_];
static __device__ __nv_bfloat16 g_vb  [(size_t)M_ * E_];
static __device__ __nv_bfloat16 g_ctxb[(size_t)M_ * E_];   // attn out [B,S,E]
static __device__ __nv_bfloat16 g_n2b [(size_t)M_ * E_];   // LN2 out
static __device__ __nv_bfloat16 g_hb  [(size_t)M_ * FF2];  // FFN hidden
static __device__ float         g_x1  [(size_t)M_ * E_];   // residual-1 (fp32)
// transposed bf16 weights, layout [N][K]
static __device__ __nv_bfloat16 g_wtq[E_ * E_];
static __device__ __nv_bfloat16 g_wtk[E_ * E_];
static __device__ __nv_bfloat16 g_wtv[E_ * E_];
static __device__ __nv_bfloat16 g_wto[E_ * E_];
static __device__ __nv_bfloat16 g_wt1[(size_t)FF2 * E_];   // [2048][512]
static __device__ __nv_bfloat16 g_wt2[(size_t)E_ * FF2];   // [512][2048]

// ---------------------------------------------------------------------------
// PTX helpers (family-portable only: cp.async, ldmatrix, mma.sync)
// ---------------------------------------------------------------------------
__device__ __forceinline__ uint32_t smem_u32(const void* p) {
    return (uint32_t)__cvta_generic_to_shared(p);
}
__device__ __forceinline__ void cp_async16_s(uint32_t saddr, const void* g) {
    asm volatile("cp.async.cg.shared.global [%0], [%1], 16;"
                 :: "r"(saddr), "l"(g));
}
#define CP_COMMIT() asm volatile("cp.async.commit_group;" ::: "memory")
#define CP_WAIT0()  asm volatile("cp.async.wait_group 0;" ::: "memory")
#define CP_WAIT1()  asm volatile("cp.async.wait_group 1;" ::: "memory")
#define CP_WAIT2()  asm volatile("cp.async.wait_group 2;" ::: "memory")

// bf16 m16n8k16 mma.sync
__device__ __forceinline__ void mma_bf16(float c[4], const uint32_t a[4],
                                         uint32_t b0, uint32_t b1)
{
    asm volatile(
        "mma.sync.aligned.m16n8k16.row.col.f32.bf16.bf16.f32 "
        "{%0,%1,%2,%3}, {%4,%5,%6,%7}, {%8,%9}, {%0,%1,%2,%3};"
        : "+f"(c[0]), "+f"(c[1]), "+f"(c[2]), "+f"(c[3])
        : "r"(a[0]), "r"(a[1]), "r"(a[2]), "r"(a[3]), "r"(b0), "r"(b1));
}
__device__ __forceinline__ void ldsm_x4_u(uint32_t r[4], uint32_t saddr) {
    asm volatile("ldmatrix.sync.aligned.m8n8.x4.shared.b16 {%0,%1,%2,%3}, [%4];"
        : "=r"(r[0]), "=r"(r[1]), "=r"(r[2]), "=r"(r[3]) : "r"(saddr));
}
__device__ __forceinline__ void ldsm_x4(uint32_t r[4], const void* p) {
    ldsm_x4_u(r, smem_u32(p));
}
__device__ __forceinline__ void ldsm_x4_t(uint32_t r[4], const void* p) {
    uint32_t s = smem_u32(p);
    asm volatile("ldmatrix.sync.aligned.m8n8.x4.trans.shared.b16 {%0,%1,%2,%3}, [%4];"
        : "=r"(r[0]), "=r"(r[1]), "=r"(r[2]), "=r"(r[3]) : "r"(s));
}

// ---------------------------------------------------------------------------
// Merged weight transpose + bf16 convert: fp32 [K,N] -> bf16 [N,K], ONE launch.
// Flat block id selects weight + tile:
//   [0,256)     wq   [256,512) wk   [512,768) wv   [768,1024) wo   (512x512)
//   [1024,2048) w1 (512x2048)       [2048,3072) w2 (2048x512)
// ---------------------------------------------------------------------------
__global__ void wtrans_all(const float* __restrict__ wq, const float* __restrict__ wk,
                           const float* __restrict__ wv, const float* __restrict__ wo,
                           const float* __restrict__ w1, const float* __restrict__ w2)
{
    int bid = blockIdx.x;
    const float* in; __nv_bfloat16* out; int K, N, tile;
    if (bid < 1024) {
        int w = bid >> 8; tile = bid & 255; K = E_; N = E_;
        in  = (w == 0) ? wq : (w == 1) ? wk : (w == 2) ? wv : wo;
        out = (w == 0) ? g_wtq : (w == 1) ? g_wtk : (w == 2) ? g_wtv : g_wto;
    } else if (bid < 2048) {
        tile = bid - 1024; K = E_; N = FF2; in = w1; out = g_wt1;
    } else {
        tile = bid - 2048; K = FF2; N = E_; in = w2; out = g_wt2;
    }
    int tilesX = N >> 5;
    int bx = (tile % tilesX) << 5, by = (tile / tilesX) << 5;
    __shared__ float t[32][33];
    int tx = threadIdx.x, ty = threadIdx.y;          // 32 x 8
    #pragma unroll
    for (int j = 0; j < 32; j += 8)
        t[ty + j][tx] = in[(size_t)(by + ty + j) * N + bx + tx];
    __syncthreads();
    #pragma unroll
    for (int j = 0; j < 32; j += 8)
        out[(size_t)(bx + ty + j) * K + by + tx] = __float2bfloat16(t[tx][ty + j]);
}

// ---------------------------------------------------------------------------
// LayerNorm (mean + unbiased std ddof=1, eps on std) -> bf16 output
// ---------------------------------------------------------------------------
__global__ void ln_kernel(const float* __restrict__ xext,
                          const float* __restrict__ alpha,
                          const float* __restrict__ beta, int which)
{
    const float* x      = (which == 0) ? xext : g_x1;
    __nv_bfloat16* out  = (which == 0) ? g_nb : g_n2b;
    int row = blockIdx.x;
    int t   = threadIdx.x;
    float4 v = ((const float4*)(x + (size_t)row * E_))[t];
    float s  = v.x + v.y + v.z + v.w;
    float sq = v.x*v.x + v.y*v.y + v.z*v.z + v.w*v.w;
    #pragma unroll
    for (int o = 16; o; o >>= 1) {
        s  += __shfl_xor_sync(0xffffffffu, s,  o);
        sq += __shfl_xor_sync(0xffffffffu, sq, o);
    }
    __shared__ float ss[4], sqs[4];
    int w = t >> 5;
    if ((t & 31) == 0) { ss[w] = s; sqs[w] = sq; }
    __syncthreads();
    s  = ss[0] + ss[1] + ss[2] + ss[3];
    sq = sqs[0] + sqs[1] + sqs[2] + sqs[3];
    float mean = s * (1.0f / E_);
    float var  = fmaxf((sq - (float)E_ * mean * mean) * (1.0f / (E_ - 1)), 0.0f);
    float scal = alpha[0] / (sqrtf(var) + 1e-6f);
    float b    = beta[0];
    __nv_bfloat162 o0 = __floats2bfloat162_rn((v.x - mean) * scal + b,
                                              (v.y - mean) * scal + b);
    __nv_bfloat162 o1 = __floats2bfloat162_rn((v.z - mean) * scal + b,
                                              (v.w - mean) * scal + b);
    uint2 pk = make_uint2(*(uint32_t*)&o0, *(uint32_t*)&o1);
    ((uint2*)(out + (size_t)row * E_))[t] = pk;
}

// ---------------------------------------------------------------------------
// Epilogue functors: (m, n, v0, v1) = two adjacent-n fp32 accumulator values
// ---------------------------------------------------------------------------
struct EpiQKV3 {                // z selects q/k/v; bf16 out in [B,H,S,DH]
    const float *bq, *bk, *bv;
    __device__ __forceinline__ void operator()(int m, int n, float v0, float v1) const {
        int z = blockIdx.z;
        const float* bias  = (z == 0) ? bq : (z == 1) ? bk : bv;
        __nv_bfloat16* out = (z == 0) ? g_qb : (z == 1) ? g_kb : g_vb;
        int b = m >> 11, s = m & (S_ - 1);
        int h = n >> 6,  d = n & 63;
        __nv_bfloat162 o = __floats2bfloat162_rn(v0 + bias[n], v1 + bias[n + 1]);
        *(__nv_bfloat162*)(out + ((((size_t)b * H_ + h) * S_ + s) * DH_ + d)) = o;
    }
};
struct EpiOProj {               // g_x1 = x + ctx@wo + bo   (fp32)
    const float* bias; const float* resid;
    __device__ __forceinline__ void operator()(int m, int n, float v0, float v1) const {
        size_t idx = (size_t)m * E_ + n;
        float2 r = *(const float2*)(resid + idx);
        *(float2*)(g_x1 + idx) =
            make_float2(v0 + bias[n] + r.x, v1 + bias[n + 1] + r.y);
    }
};
struct EpiRelu {                // g_hb = relu(n2@w1 + b1)  (bf16)
    const float* bias;
    __device__ __forceinline__ void operator()(int m, int n, float v0, float v1) const {
        __nv_bfloat162 o = __floats2bfloat162_rn(fmaxf(v0 + bias[n],     0.f),
                                                 fmaxf(v1 + bias[n + 1], 0.f));
        *(__nv_bfloat162*)(g_hb + (size_t)m * FF2 + n) = o;
    }
};
struct EpiFinal {               // out = x1 + h@w2 + b2     (fp32)
    float* out; const float* bias;
    __device__ __forceinline__ void operator()(int m, int n, float v0, float v1) const {
        size_t idx = (size_t)m * E_ + n;
        float2 r = *(const float2*)(g_x1 + idx);
        *(float2*)(out + idx) =
            make_float2(v0 + bias[n] + r.x, v1 + bias[n + 1] + r.y);
    }
};

__device__ __forceinline__ const __nv_bfloat16* gemm_A(int s) {
    return (s == 0) ? g_nb : (s == 1) ? g_ctxb : (s == 2) ? g_n2b : g_hb;
}
__device__ __forceinline__ const __nv_bfloat16* gemm_W(int s) {
    return (s == 0) ? g_wtq : (s == 1) ? g_wtk : (s == 2) ? g_wtv
         : (s == 3) ? g_wto : (s == 4) ? g_wt1 : g_wt2;
}

// ---------------------------------------------------------------------------
// bf16 mma.sync GEMM: C[M,N] = A[M,K] @ Wt[N,K]^T  (+ epilogue)
// CTA tile 128x128, BK=32, 256 threads = 8 warps (4m x 2n), warp tile 32x64.
// 4-stage cp.async pipeline. All fragments via ldmatrix.x4.
// Row stride 80 B: bank group (5r+g) mod 8 is a permutation -> conflict-free.
// ---------------------------------------------------------------------------
#define G_ROWB       80
#define GA_BYTES     (128 * G_ROWB)          // 10240
#define GSTAGE_BYTES (2 * GA_BYTES)          // 20480
#define GT_SMEM      (4 * GSTAGE_BYTES)      // 81920

template <class Epi>
__global__ void __launch_bounds__(256, 2)
gemm_bf16(int asel, int wsel0, int K, int N, Epi epi)
{
    extern __shared__ char smem[];
    uint32_t sb = smem_u32(smem);
    const __nv_bfloat16* A = gemm_A(asel);
    const __nv_bfloat16* W = gemm_W(wsel0 + blockIdx.z);
    int m0 = blockIdx.y * 128, n0 = blockIdx.x * 128;
    int tid = threadIdx.x, wid = tid >> 5, lane = tid & 31;
    int g = lane >> 2, t = lane & 3;
    int wm = wid & 3, wn = wid >> 2;
    // ldmatrix lane offsets
    int arow = lane & 15;                        // A: rows 0..15
    int acol = (lane >> 4) << 3;                 // A: k halves
    int brow = ((lane >> 4) << 3) + (lane & 7);  // B: n offset 0..15
    int bcol = ((lane >> 3) & 1) << 3;           // B: k halves

    const __nv_bfloat16* Ab = A + (size_t)m0 * K;
    const __nv_bfloat16* Wb = W + (size_t)n0 * K;
    const int NC = K >> 5;                       // BK=32 chunks

    auto load_chunk = [&](int ci) {
        uint32_t base = sb + (ci & 3) * GSTAGE_BYTES;
        const __nv_bfloat16* Ap = Ab + ci * 32;
        const __nv_bfloat16* Wp = Wb + ci * 32;
        #pragma unroll
        for (int i = 0; i < 2; i++) {            // 512 rows*4 groups / 256 thr
            int idx = tid + i * 256;
            int r = idx >> 2, cg = idx & 3;
            cp_async16_s(base + r * G_ROWB + cg * 16,
                         Ap + (size_t)r * K + cg * 8);
            cp_async16_s(base + GA_BYTES + r * G_ROWB + cg * 16,
                         Wp + (size_t)r * K + cg * 8);
        }
    };

    float acc[2][8][4];
    #pragma unroll
    for (int mt = 0; mt < 2; mt++)
        #pragma unroll
        for (int nt = 0; nt < 8; nt++)
            #pragma unroll
            for (int i = 0; i < 4; i++) acc[mt][nt][i] = 0.f;

    load_chunk(0); CP_COMMIT();
    load_chunk(1); CP_COMMIT();
    load_chunk(2); CP_COMMIT();

    for (int i = 0; i < NC; i++) {
        if (i + 2 < NC)      CP_WAIT2();
        else if (i + 1 < NC) CP_WAIT1();
        else                 CP_WAIT0();
        __syncthreads();                 // chunk i visible; buf (i-1)%4 free
        if (i + 3 < NC) { load_chunk(i + 3); CP_COMMIT(); }

        uint32_t abase = sb + (i & 3) * GSTAGE_BYTES;
        uint32_t bbase = abase + GA_BYTES;
        #pragma unroll
        for (int ks = 0; ks < 2; ks++) {
            int kk = ks * 16;
            uint32_t a[2][4];
            #pragma unroll
            for (int mt = 0; mt < 2; mt++)
                ldsm_x4_u(a[mt], abase + (wm * 32 + mt * 16 + arow) * G_ROWB
                                        + (kk + acol) * 2);
            #pragma unroll
            for (int np = 0; np < 4; np++) {
                uint32_t bfr[4];
                ldsm_x4_u(bfr, bbase + (wn * 64 + np * 16 + brow) * G_ROWB
                                      + (kk + bcol) * 2);
                #pragma unroll
                for (int mt = 0; mt < 2; mt++) {
                    mma_bf16(acc[mt][2*np],     a[mt], bfr[0], bfr[1]);
                    mma_bf16(acc[mt][2*np + 1], a[mt], bfr[2], bfr[3]);
                }
            }
        }
    }

    #pragma unroll
    for (int mt = 0; mt < 2; mt++) {
        int rb = m0 + wm * 32 + mt * 16;
        #pragma unroll
        for (int nt = 0; nt < 8; nt++) {
            int n = n0 + wn * 64 + nt * 8 + 2 * t;
            epi(rb + g,     n, acc[mt][nt][0], acc[mt][nt][1]);
            epi(rb + g + 8, n, acc[mt][nt][2], acc[mt][nt][3]);
        }
    }
}

// ---------------------------------------------------------------------------
// Flash attention, bf16 m16n8k16 mma.sync.
// One CTA = 128 queries of one (b,h), 256 threads = 8 warps, warp w owns
// q rows [16w, 16w+16). K/V chunks of 64 keys in a 3-stage cp.async ring
// (issue-at-top keeps 2 chunks in flight during compute).
// smem rows stride 144 B: Ks[3][64], Vs[3][64], Ps[128] (Q staging, then P).
// ---------------------------------------------------------------------------
#define NKV      3
#define KV_STG   (64 * 144)              // 9216
#define VS_OFF   (NKV * KV_STG)          // 27648
#define PS_OFF   (2 * NKV * KV_STG)      // 55296
#define ATTN_SMEM (PS_OFF + 128 * 144)   // 73728

__global__ void __launch_bounds__(256, 2)
attn_bf16(const int* __restrict__ mask)
{
    extern __shared__ char smem[];
    uint32_t sb = smem_u32(smem);

    int tid  = threadIdx.x;
    int wid  = tid >> 5, lane = tid & 31;
    int g    = lane >> 2, t = lane & 3;
    int qb   = wid * 16;
    // ldmatrix lane offsets
    int arow = lane & 15;                  // A frag row
    int acol = (lane >> 4) << 3;           // A frag col (elems)
    int kbr  = ((lane >> 4) << 3) + (lane & 7);        // K B-frag: n offset
    int kbc  = ((lane >> 3) & 1) << 3;                 // K B-frag: k offset
    int vbr  = (((lane >> 3) & 1) << 3) + (lane & 7);  // V trans: j offset
    int vbc  = (lane >> 4) << 3;                       // V trans: d offset

    int bh = blockIdx.y;
    int q0 = blockIdx.x * 128;
    int bb = bh >> 3, hh = bh & 7;
    const __nv_bfloat16* Qb = g_qb + (size_t)bh * S_ * DH_;
    const __nv_bfloat16* Kb = g_kb + (size_t)bh * S_ * DH_;
    const __nv_bfloat16* Vb = g_vb + (size_t)bh * S_ * DH_;
    const int* mrow = mask + bb * S_;

    auto load_kv = [&](int ci) {
        uint32_t st = (uint32_t)(ci % NKV) * KV_STG;
        #pragma unroll
        for (int i = 0; i < 2; i++) {               // 512 16B-chunks / 256 thr
            int idx = tid + i * 256;
            int r = idx >> 3, cB = (idx & 7) << 4;
            cp_async16_s(sb + st + r * 144 + cB,
                         Kb + (size_t)(ci * 64 + r) * DH_ + (cB >> 1));
            cp_async16_s(sb + VS_OFF + st + r * 144 + cB,
                         Vb + (size_t)(ci * 64 + r) * DH_ + (cB >> 1));
        }
    };

    // stage Q into Ps (128 rows)
    #pragma unroll
    for (int i = 0; i < 4; i++) {
        int idx = tid + i * 256;
        int r = idx >> 3, cB = (idx & 7) << 4;
        cp_async16_s(sb + PS_OFF + r * 144 + cB,
                     Qb + (size_t)(q0 + r) * DH_ + (cB >> 1));
    }
    CP_COMMIT();
    load_kv(0); CP_COMMIT();
    load_kv(1); CP_COMMIT();

    CP_WAIT2();                 // Q resident
    __syncthreads();
    uint32_t qa[4][4];
    #pragma unroll
    for (int ks = 0; ks < 4; ks++)
        ldsm_x4_u(qa[ks], sb + PS_OFF + (qb + arow) * 144 + (ks * 16 + acol) * 2);

    float oacc[8][4];
    #pragma unroll
    for (int nt = 0; nt < 8; nt++)
        #pragma unroll
        for (int i = 0; i < 4; i++) oacc[nt][i] = 0.f;
    float mi[2] = { -INFINITY, -INFINITY };
    float li[2] = { 0.f, 0.f };

    const int NC = S_ / 64;
    for (int i = 0; i < NC; i++) {
        __syncthreads();        // all warps done with stage (i+2)%3's old chunk
        if (i + 2 < NC) { load_kv(i + 2); CP_COMMIT(); }
        if (i + 2 < NC)      CP_WAIT2();
        else if (i + 1 < NC) CP_WAIT1();
        else                 CP_WAIT0();
        __syncthreads();        // chunk i visible to all warps
        uint32_t kst = sb + (uint32_t)(i % NKV) * KV_STG;
        uint32_t vst = kst + VS_OFF;
        int kt = i * 64;

        // S = Q @ K^T  (K tile [j][d] = n-major -> native B frags)
        float sacc[8][4];
        #pragma unroll
        for (int nt = 0; nt < 8; nt++)
            #pragma unroll
            for (int j = 0; j < 4; j++) sacc[nt][j] = 0.f;
        #pragma unroll
        for (int ks = 0; ks < 4; ks++) {
            int kk = ks * 16;
            #pragma unroll
            for (int np = 0; np < 4; np++) {
                uint32_t bfr[4];
                ldsm_x4_u(bfr, kst + (np * 16 + kbr) * 144 + (kk + kbc) * 2);
                mma_bf16(sacc[2*np],     qa[ks], bfr[0], bfr[1]);
                mma_bf16(sacc[2*np + 1], qa[ks], bfr[2], bfr[3]);
            }
        }

        // scale, mask
        #pragma unroll
        for (int nt = 0; nt < 8; nt++) {
            #pragma unroll
            for (int j = 0; j < 4; j++) sacc[nt][j] *= 0.125f;
            int jg = kt + nt * 8 + 2 * t;
            if (__ldg(mrow + jg)     == 0) { sacc[nt][0] = -1e9f; sacc[nt][2] = -1e9f; }
            if (__ldg(mrow + jg + 1) == 0) { sacc[nt][1] = -1e9f; sacc[nt][3] = -1e9f; }
        }

        // online softmax (rows g, g+8; stats shared across 4 t-lanes)
        #pragma unroll
        for (int h = 0; h < 2; h++) {
            float rm = -INFINITY;
            #pragma unroll
            for (int nt = 0; nt < 8; nt++)
                rm = fmaxf(rm, fmaxf(sacc[nt][2*h], sacc[nt][2*h + 1]));
            rm = fmaxf(rm, __shfl_xor_sync(0xffffffffu, rm, 1));
            rm = fmaxf(rm, __shfl_xor_sync(0xffffffffu, rm, 2));
            float mnew = fmaxf(mi[h], rm);
            float corr = __expf(mi[h] - mnew);
            mi[h] = mnew;
            float rs = 0.f;
            #pragma unroll
            for (int nt = 0; nt < 8; nt++) {
                float e0 = __expf(sacc[nt][2*h]     - mnew);
                float e1 = __expf(sacc[nt][2*h + 1] - mnew);
                sacc[nt][2*h]     = e0;
                sacc[nt][2*h + 1] = e1;
                rs += e0 + e1;
            }
            rs += __shfl_xor_sync(0xffffffffu, rs, 1);
            rs += __shfl_xor_sync(0xffffffffu, rs, 2);
            li[h] = li[h] * corr + rs;
            #pragma unroll
            for (int nt = 0; nt < 8; nt++) {
                oacc[nt][2*h]     *= corr;
                oacc[nt][2*h + 1] *= corr;
            }
        }

        // P -> smem (bf16). Each warp only touches its own 16 rows.
        #pragma unroll
        for (int nt = 0; nt < 8; nt++) {
            int jc = nt * 8 + 2 * t;
            *(__nv_bfloat162*)(smem + PS_OFF + (qb + g) * 144 + jc * 2) =
                __floats2bfloat162_rn(sacc[nt][0], sacc[nt][1]);
            *(__nv_bfloat162*)(smem + PS_OFF + (qb + g + 8) * 144 + jc * 2) =
                __floats2bfloat162_rn(sacc[nt][2], sacc[nt][3]);
        }
        __syncwarp();

        // O += P @ V  (V tile [j][d] -> trans ldsm gives [d][j] B frags)
        #pragma unroll
        for (int js = 0; js < 4; js++) {
            int j0 = js * 16;
            uint32_t a[4];
            ldsm_x4_u(a, sb + PS_OFF + (qb + arow) * 144 + (j0 + acol) * 2);
            #pragma unroll
            for (int np = 0; np < 4; np++) {
                uint32_t bfr[4];
                ldsm_x4_t(bfr, smem + vst - sb + (j0 + vbr) * 144
                                             + (np * 16 + vbc) * 2);
                mma_bf16(oacc[2*np],     a, bfr[0], bfr[1]);
                mma_bf16(oacc[2*np + 1], a, bfr[2], bfr[3]);
            }
        }
    }

    // finalize: 1/l, write bf16 ctx in [B,S,E] layout
    #pragma unroll
    for (int h = 0; h < 2; h++) {
        float inv = 1.0f / li[h];
        int r = q0 + qb + g + 8 * h;
        __nv_bfloat16* orow = g_ctxb + ((size_t)bb * S_ + r) * E_ + hh * DH_;
        #pragma unroll
        for (int nt = 0; nt < 8; nt++) {
            int d = nt * 8 + 2 * t;
            *(__nv_bfloat162*)(orow + d) =
                __floats2bfloat162_rn(oacc[nt][2*h] * inv, oacc[nt][2*h + 1] * inv);
        }
    }
}

// ---------------------------------------------------------------------------
// kernel_launch: graph-capturable, no allocations
// ---------------------------------------------------------------------------
extern "C" void kernel_launch(void* const* d_in, const int* in_sizes, int n_in,
                              void* d_out, int out_size)
{
    const float* x    = (const float*)d_in[0];
    const int*   mask = (const int*)  d_in[1];
    const float* wq   = (const float*)d_in[2];
    const float* bq   = (const float*)d_in[3];
    const float* wk   = (const float*)d_in[4];
    const float* bk   = (const float*)d_in[5];
    const float* wv   = (const float*)d_in[6];
    const float* bv   = (const float*)d_in[7];
    const float* wo   = (const float*)d_in[8];
    const float* bo   = (const float*)d_in[9];
    const float* w1   = (const float*)d_in[10];
    const float* b1   = (const float*)d_in[11];
    const float* w2   = (const float*)d_in[12];
    const float* b2   = (const float*)d_in[13];
    const float* al1  = (const float*)d_in[14];
    const float* be1  = (const float*)d_in[15];
    const float* al2  = (const float*)d_in[16];
    const float* be2  = (const float*)d_in[17];
    float* out = (float*)d_out;

    cudaFuncSetAttribute(gemm_bf16<EpiQKV3>,
        cudaFuncAttributeMaxDynamicSharedMemorySize, GT_SMEM);
    cudaFuncSetAttribute(gemm_bf16<EpiOProj>,
        cudaFuncAttributeMaxDynamicSharedMemorySize, GT_SMEM);
    cudaFuncSetAttribute(gemm_bf16<EpiRelu>,
        cudaFuncAttributeMaxDynamicSharedMemorySize, GT_SMEM);
    cudaFuncSetAttribute(gemm_bf16<EpiFinal>,
        cudaFuncAttributeMaxDynamicSharedMemorySize, GT_SMEM);
    cudaFuncSetAttribute(attn_bf16,
        cudaFuncAttributeMaxDynamicSharedMemorySize, ATTN_SMEM);

    // all six weight transposes in ONE launch
    wtrans_all<<<3072, dim3(32, 8)>>>(wq, wk, wv, wo, w1, w2);

    // norm1
    ln_kernel<<<M_, 128>>>(x, al1, be1, 0);

    // Q/K/V projections (one launch, z selects weight/out)
    dim3 gqkv(E_ / 128, M_ / 128, 3);
    gemm_bf16<EpiQKV3><<<gqkv, 256, GT_SMEM>>>(
        0, 0, E_, E_, EpiQKV3{bq, bk, bv});

    // attention (128 queries per CTA)
    dim3 ga(S_ / 128, B_ * H_);
    attn_bf16<<<ga, 256, ATTN_SMEM>>>(mask);

    // O projection + residual 1
    dim3 g512(E_ / 128, M_ / 128, 1);
    gemm_bf16<EpiOProj><<<g512, 256, GT_SMEM>>>(
        1, 3, E_, E_, EpiOProj{bo, x});

    // norm2
    ln_kernel<<<M_, 128>>>(nullptr, al2, be2, 1);

    // FFN1 (N=2048) with ReLU
    dim3 gff1(FF2 / 128, M_ / 128, 1);
    gemm_bf16<EpiRelu><<<gff1, 256, GT_SMEM>>>(
        2, 4, E_, FF2, EpiRelu{b1});

    // FFN2 (K=2048) + residual 2 -> final output
    gemm_bf16<EpiFinal><<<g512, 256, GT_SMEM>>>(
        3, 5, FF2, E_, EpiFinal{out, b2});
}

// round 14
// speedup vs baseline: 1.1361x; 1.1361x over previous
#include <cuda_runtime.h>
#include <cuda_bf16.h>
#include <math.h>
#include <stdint.h>

// Problem dims (fixed by the reference)
#define B_   4
#define S_   2048
#define E_   512
#define H_   8
#define DH_  64
#define FF2  2048
#define M_   8192   // B_*S_

// ---------------------------------------------------------------------------
// Scratch buffers (device globals -- no allocations allowed)
// ---------------------------------------------------------------------------
static __device__ __nv_bfloat16 g_nb  [(size_t)M_ * E_];   // LN1 out
static __device__ __nv_bfloat16 g_qb  [(size_t)M_ * E_];   // [B,H,S,DH] (prescaled)
static __device__ __nv_bfloat16 g_kb  [(size_t)M_ * E_];
static __device__ __nv_bfloat16 g_vb  [(size_t)M_ * E_];
static __device__ __nv_bfloat16 g_ctxb[(size_t)M_ * E_];   // attn out [B,S,E]
static __device__ __nv_bfloat16 g_n2b [(size_t)M_ * E_];   // LN2 out
static __device__ __nv_bfloat16 g_hb  [(size_t)M_ * FF2];  // FFN hidden
static __device__ float         g_x1  [(size_t)M_ * E_];   // residual-1 (fp32)
// transposed bf16 weights, layout [N][K]
static __device__ __nv_bfloat16 g_wtq[E_ * E_];
static __device__ __nv_bfloat16 g_wtk[E_ * E_];
static __device__ __nv_bfloat16 g_wtv[E_ * E_];
static __device__ __nv_bfloat16 g_wto[E_ * E_];
static __device__ __nv_bfloat16 g_wt1[(size_t)FF2 * E_];   // [2048][512]
static __device__ __nv_bfloat16 g_wt2[(size_t)E_ * FF2];   // [512][2048]

// 0.125 * log2(e): folded into Q so QK scores land in log2 domain
#define QSCALE 0.18033688011112042f

// ---------------------------------------------------------------------------
// PTX helpers (family-portable only: cp.async, ldmatrix, mma.sync)
// ---------------------------------------------------------------------------
__device__ __forceinline__ uint32_t smem_u32(const void* p) {
    return (uint32_t)__cvta_generic_to_shared(p);
}
__device__ __forceinline__ void cp_async16_s(uint32_t saddr, const void* g) {
    asm volatile("cp.async.cg.shared.global [%0], [%1], 16;"
                 :: "r"(saddr), "l"(g));
}
#define CP_COMMIT() asm volatile("cp.async.commit_group;" ::: "memory")
#define CP_WAIT0()  asm volatile("cp.async.wait_group 0;" ::: "memory")
#define CP_WAIT1()  asm volatile("cp.async.wait_group 1;" ::: "memory")
#define CP_WAIT2()  asm volatile("cp.async.wait_group 2;" ::: "memory")

__device__ __forceinline__ float ex2f(float x) {
    float r;
    asm("ex2.approx.ftz.f32 %0, %1;" : "=f"(r) : "f"(x));
    return r;
}

// bf16 m16n8k16 mma.sync
__device__ __forceinline__ void mma_bf16(float c[4], const uint32_t a[4],
                                         uint32_t b0, uint32_t b1)
{
    asm volatile(
        "mma.sync.aligned.m16n8k16.row.col.f32.bf16.bf16.f32 "
        "{%0,%1,%2,%3}, {%4,%5,%6,%7}, {%8,%9}, {%0,%1,%2,%3};"
        : "+f"(c[0]), "+f"(c[1]), "+f"(c[2]), "+f"(c[3])
        : "r"(a[0]), "r"(a[1]), "r"(a[2]), "r"(a[3]), "r"(b0), "r"(b1));
}
__device__ __forceinline__ void ldsm_x4_u(uint32_t r[4], uint32_t saddr) {
    asm volatile("ldmatrix.sync.aligned.m8n8.x4.shared.b16 {%0,%1,%2,%3}, [%4];"
        : "=r"(r[0]), "=r"(r[1]), "=r"(r[2]), "=r"(r[3]) : "r"(saddr));
}
__device__ __forceinline__ void ldsm_x4_t_u(uint32_t r[4], uint32_t saddr) {
    asm volatile("ldmatrix.sync.aligned.m8n8.x4.trans.shared.b16 {%0,%1,%2,%3}, [%4];"
        : "=r"(r[0]), "=r"(r[1]), "=r"(r[2]), "=r"(r[3]) : "r"(saddr));
}
__device__ __forceinline__ uint32_t packbf2(float a, float b) {
    __nv_bfloat162 v = __floats2bfloat162_rn(a, b);
    return *(uint32_t*)&v;
}

// ---------------------------------------------------------------------------
// Merged weight transpose + bf16 convert: fp32 [K,N] -> bf16 [N,K], ONE launch.
// ---------------------------------------------------------------------------
__global__ void wtrans_all(const float* __restrict__ wq, const float* __restrict__ wk,
                           const float* __restrict__ wv, const float* __restrict__ wo,
                           const float* __restrict__ w1, const float* __restrict__ w2)
{
    int bid = blockIdx.x;
    const float* in; __nv_bfloat16* out; int K, N, tile;
    if (bid < 1024) {
        int w = bid >> 8; tile = bid & 255; K = E_; N = E_;
        in  = (w == 0) ? wq : (w == 1) ? wk : (w == 2) ? wv : wo;
        out = (w == 0) ? g_wtq : (w == 1) ? g_wtk : (w == 2) ? g_wtv : g_wto;
    } else if (bid < 2048) {
        tile = bid - 1024; K = E_; N = FF2; in = w1; out = g_wt1;
    } else {
        tile = bid - 2048; K = FF2; N = E_; in = w2; out = g_wt2;
    }
    int tilesX = N >> 5;
    int bx = (tile % tilesX) << 5, by = (tile / tilesX) << 5;
    __shared__ float t[32][33];
    int tx = threadIdx.x, ty = threadIdx.y;          // 32 x 8
    #pragma unroll
    for (int j = 0; j < 32; j += 8)
        t[ty + j][tx] = in[(size_t)(by + ty + j) * N + bx + tx];
    __syncthreads();
    #pragma unroll
    for (int j = 0; j < 32; j += 8)
        out[(size_t)(bx + ty + j) * K + by + tx] = __float2bfloat16(t[tx][ty + j]);
}

// ---------------------------------------------------------------------------
// LayerNorm (mean + unbiased std ddof=1, eps on std) -> bf16 output
// ---------------------------------------------------------------------------
__global__ void ln_kernel(const float* __restrict__ xext,
                          const float* __restrict__ alpha,
                          const float* __restrict__ beta, int which)
{
    const float* x      = (which == 0) ? xext : g_x1;
    __nv_bfloat16* out  = (which == 0) ? g_nb : g_n2b;
    int row = blockIdx.x;
    int t   = threadIdx.x;
    float4 v = ((const float4*)(x + (size_t)row * E_))[t];
    float s  = v.x + v.y + v.z + v.w;
    float sq = v.x*v.x + v.y*v.y + v.z*v.z + v.w*v.w;
    #pragma unroll
    for (int o = 16; o; o >>= 1) {
        s  += __shfl_xor_sync(0xffffffffu, s,  o);
        sq += __shfl_xor_sync(0xffffffffu, sq, o);
    }
    __shared__ float ss[4], sqs[4];
    int w = t >> 5;
    if ((t & 31) == 0) { ss[w] = s; sqs[w] = sq; }
    __syncthreads();
    s  = ss[0] + ss[1] + ss[2] + ss[3];
    sq = sqs[0] + sqs[1] + sqs[2] + sqs[3];
    float mean = s * (1.0f / E_);
    float var  = fmaxf((sq - (float)E_ * mean * mean) * (1.0f / (E_ - 1)), 0.0f);
    float scal = alpha[0] / (sqrtf(var) + 1e-6f);
    float b    = beta[0];
    __nv_bfloat162 o0 = __floats2bfloat162_rn((v.x - mean) * scal + b,
                                              (v.y - mean) * scal + b);
    __nv_bfloat162 o1 = __floats2bfloat162_rn((v.z - mean) * scal + b,
                                              (v.w - mean) * scal + b);
    uint2 pk = make_uint2(*(uint32_t*)&o0, *(uint32_t*)&o1);
    ((uint2*)(out + (size_t)row * E_))[t] = pk;
}

// ---------------------------------------------------------------------------
// Epilogue functors: (m, n, v0, v1) = two adjacent-n fp32 accumulator values
// ---------------------------------------------------------------------------
struct EpiQKV3 {                // z selects q/k/v; bf16 out in [B,H,S,DH]
    const float *bq, *bk, *bv;  // Q is prescaled by QSCALE (log2-domain scores)
    __device__ __forceinline__ void operator()(int m, int n, float v0, float v1) const {
        int z = blockIdx.z;
        const float* bias  = (z == 0) ? bq : (z == 1) ? bk : bv;
        __nv_bfloat16* out = (z == 0) ? g_qb : (z == 1) ? g_kb : g_vb;
        float sc = (z == 0) ? QSCALE : 1.0f;
        int b = m >> 11, s = m & (S_ - 1);
        int h = n >> 6,  d = n & 63;
        __nv_bfloat162 o = __floats2bfloat162_rn((v0 + bias[n]) * sc,
                                                 (v1 + bias[n + 1]) * sc);
        *(__nv_bfloat162*)(out + ((((size_t)b * H_ + h) * S_ + s) * DH_ + d)) = o;
    }
};
struct EpiOProj {               // g_x1 = x + ctx@wo + bo   (fp32)
    const float* bias; const float* resid;
    __device__ __forceinline__ void operator()(int m, int n, float v0, float v1) const {
        size_t idx = (size_t)m * E_ + n;
        float2 r = *(const float2*)(resid + idx);
        *(float2*)(g_x1 + idx) =
            make_float2(v0 + bias[n] + r.x, v1 + bias[n + 1] + r.y);
    }
};
struct EpiRelu {                // g_hb = relu(n2@w1 + b1)  (bf16)
    const float* bias;
    __device__ __forceinline__ void operator()(int m, int n, float v0, float v1) const {
        __nv_bfloat162 o = __floats2bfloat162_rn(fmaxf(v0 + bias[n],     0.f),
                                                 fmaxf(v1 + bias[n + 1], 0.f));
        *(__nv_bfloat162*)(g_hb + (size_t)m * FF2 + n) = o;
    }
};
struct EpiFinal {               // out = x1 + h@w2 + b2     (fp32)
    float* out; const float* bias;
    __device__ __forceinline__ void operator()(int m, int n, float v0, float v1) const {
        size_t idx = (size_t)m * E_ + n;
        float2 r = *(const float2*)(g_x1 + idx);
        *(float2*)(out + idx) =
            make_float2(v0 + bias[n] + r.x, v1 + bias[n + 1] + r.y);
    }
};

__device__ __forceinline__ const __nv_bfloat16* gemm_A(int s) {
    return (s == 0) ? g_nb : (s == 1) ? g_ctxb : (s == 2) ? g_n2b : g_hb;
}
__device__ __forceinline__ const __nv_bfloat16* gemm_W(int s) {
    return (s == 0) ? g_wtq : (s == 1) ? g_wtk : (s == 2) ? g_wtv
         : (s == 3) ? g_wto : (s == 4) ? g_wt1 : g_wt2;
}

// ---------------------------------------------------------------------------
// bf16 mma.sync GEMM: C[M,N] = A[M,K] @ Wt[N,K]^T  (+ epilogue)
// CTA tile 128x128, BK=64, 256 threads = 8 warps (4m x 2n), warp tile 32x64.
// 3-stage cp.async ring, ONE __syncthreads per chunk.
// Row stride 144 B (9 x 16B groups): (9r+c) mod 8 permutation -> ldmatrix
// conflict-free.
// ---------------------------------------------------------------------------
#define G_ROWB       144
#define GA_BYTES     (128 * G_ROWB)          // 18432
#define GSTAGE_BYTES (2 * GA_BYTES)          // 36864
#define GT_SMEM      (3 * GSTAGE_BYTES)      // 110592

template <class Epi>
__global__ void __launch_bounds__(256, 2)
gemm_bf16(int asel, int wsel0, int K, int N, Epi epi)
{
    extern __shared__ char smem[];
    uint32_t sb = smem_u32(smem);
    const __nv_bfloat16* A = gemm_A(asel);
    const __nv_bfloat16* W = gemm_W(wsel0 + blockIdx.z);
    int m0 = blockIdx.y * 128, n0 = blockIdx.x * 128;
    int tid = threadIdx.x, wid = tid >> 5, lane = tid & 31;
    int g = lane >> 2, t = lane & 3;
    int wm = wid & 3, wn = wid >> 2;
    // ldmatrix lane offsets
    int arow = lane & 15;                        // A: rows 0..15
    int acol = (lane >> 4) << 3;                 // A: k halves
    int brow = ((lane >> 4) << 3) + (lane & 7);  // B: n offset 0..15
    int bcol = ((lane >> 3) & 1) << 3;           // B: k halves

    const __nv_bfloat16* Ab = A + (size_t)m0 * K;
    const __nv_bfloat16* Wb = W + (size_t)n0 * K;
    const int NC = K >> 6;                       // BK=64 chunks

    auto load_chunk = [&](int ci) {
        uint32_t base = sb + (uint32_t)(ci % 3) * GSTAGE_BYTES;
        const __nv_bfloat16* Ap = Ab + ci * 64;
        const __nv_bfloat16* Wp = Wb + ci * 64;
        #pragma unroll
        for (int i = 0; i < 4; i++) {            // 1024 16B-groups / 256 thr
            int idx = tid + i * 256;
            int r = idx >> 3, cg = idx & 7;
            cp_async16_s(base + r * G_ROWB + cg * 16,
                         Ap + (size_t)r * K + cg * 8);
            cp_async16_s(base + GA_BYTES + r * G_ROWB + cg * 16,
                         Wp + (size_t)r * K + cg * 8);
        }
    };

    float acc[2][8][4];
    #pragma unroll
    for (int mt = 0; mt < 2; mt++)
        #pragma unroll
        for (int nt = 0; nt < 8; nt++)
            #pragma unroll
            for (int i = 0; i < 4; i++) acc[mt][nt][i] = 0.f;

    load_chunk(0); CP_COMMIT();
    if (NC > 1) { load_chunk(1); CP_COMMIT(); }

    for (int i = 0; i < NC; i++) {
        if (i + 1 < NC) CP_WAIT1(); else CP_WAIT0();
        __syncthreads();                 // chunk i visible; all done chunk i-1
        if (i + 2 < NC) { load_chunk(i + 2); CP_COMMIT(); }

        uint32_t abase = sb + (uint32_t)(i % 3) * GSTAGE_BYTES;
        uint32_t bbase = abase + GA_BYTES;
        #pragma unroll
        for (int ks = 0; ks < 4; ks++) {
            int kk = ks * 16;
            uint32_t a[2][4];
            #pragma unroll
            for (int mt = 0; mt < 2; mt++)
                ldsm_x4_u(a[mt], abase + (wm * 32 + mt * 16 + arow) * G_ROWB
                                        + (kk + acol) * 2);
            #pragma unroll
            for (int np = 0; np < 4; np++) {
                uint32_t bfr[4];
                ldsm_x4_u(bfr, bbase + (wn * 64 + np * 16 + brow) * G_ROWB
                                      + (kk + bcol) * 2);
                #pragma unroll
                for (int mt = 0; mt < 2; mt++) {
                    mma_bf16(acc[mt][2*np],     a[mt], bfr[0], bfr[1]);
                    mma_bf16(acc[mt][2*np + 1], a[mt], bfr[2], bfr[3]);
                }
            }
        }
    }

    #pragma unroll
    for (int mt = 0; mt < 2; mt++) {
        int rb = m0 + wm * 32 + mt * 16;
        #pragma unroll
        for (int nt = 0; nt < 8; nt++) {
            int n = n0 + wn * 64 + nt * 8 + 2 * t;
            epi(rb + g,     n, acc[mt][nt][0], acc[mt][nt][1]);
            epi(rb + g + 8, n, acc[mt][nt][2], acc[mt][nt][3]);
        }
    }
}

// ---------------------------------------------------------------------------
// Flash attention, bf16 m16n8k16 mma.sync, FA2 register-P (no P smem).
// One CTA = 128 queries of one (b,h), 256 threads = 8 warps, warp w owns
// q rows [16w, 16w+16). 64-key chunks in a 3-stage cp.async ring, ONE sync
// per chunk. Scores arrive in log2 domain (Q prescaled by 0.125*log2e);
// softmax uses raw ex2.approx.
// smem rows stride 144 B: Ks[3][64], Vs[3][64], Qs[128].
// ---------------------------------------------------------------------------
#define NKV      3
#define KV_STG   (64 * 144)              // 9216
#define VS_OFF   (NKV * KV_STG)          // 27648
#define QS_OFF   (2 * NKV * KV_STG)      // 55296
#define ATTN_SMEM (QS_OFF + 128 * 144)   // 73728

__global__ void __launch_bounds__(256, 2)
attn_bf16(const int* __restrict__ mask)
{
    extern __shared__ char smem[];
    uint32_t sb = smem_u32(smem);

    int tid  = threadIdx.x;
    int wid  = tid >> 5, lane = tid & 31;
    int g    = lane >> 2, t = lane & 3;
    int qb   = wid * 16;
    // ldmatrix lane offsets
    int arow = lane & 15;                  // A frag row
    int acol = (lane >> 4) << 3;           // A frag col (elems)
    int kbr  = ((lane >> 4) << 3) + (lane & 7);        // K B-frag: n offset
    int kbc  = ((lane >> 3) & 1) << 3;                 // K B-frag: k offset
    int vbr  = (((lane >> 3) & 1) << 3) + (lane & 7);  // V trans: j offset
    int vbc  = (lane >> 4) << 3;                       // V trans: d offset

    int bh = blockIdx.y;
    int q0 = blockIdx.x * 128;
    int bb = bh >> 3, hh = bh & 7;
    const __nv_bfloat16* Qb = g_qb + (size_t)bh * S_ * DH_;
    const __nv_bfloat16* Kb = g_kb + (size_t)bh * S_ * DH_;
    const __nv_bfloat16* Vb = g_vb + (size_t)bh * S_ * DH_;
    const int* mrow = mask + bb * S_;

    auto load_kv = [&](int ci) {
        uint32_t st = (uint32_t)(ci % NKV) * KV_STG;
        #pragma unroll
        for (int i = 0; i < 2; i++) {               // 512 16B-chunks / 256 thr
            int idx = tid + i * 256;
            int r = idx >> 3, cB = (idx & 7) << 4;
            cp_async16_s(sb + st + r * 144 + cB,
                         Kb + (size_t)(ci * 64 + r) * DH_ + (cB >> 1));
            cp_async16_s(sb + VS_OFF + st + r * 144 + cB,
                         Vb + (size_t)(ci * 64 + r) * DH_ + (cB >> 1));
        }
    };

    // stage Q (prescaled in projection) into Qs (128 rows)
    #pragma unroll
    for (int i = 0; i < 4; i++) {
        int idx = tid + i * 256;
        int r = idx >> 3, cB = (idx & 7) << 4;
        cp_async16_s(sb + QS_OFF + r * 144 + cB,
                     Qb + (size_t)(q0 + r) * DH_ + (cB >> 1));
    }
    CP_COMMIT();
    load_kv(0); CP_COMMIT();
    load_kv(1); CP_COMMIT();

    CP_WAIT2();                 // Q resident
    __syncthreads();
    uint32_t qa[4][4];
    #pragma unroll
    for (int ks = 0; ks < 4; ks++)
        ldsm_x4_u(qa[ks], sb + QS_OFF + (qb + arow) * 144 + (ks * 16 + acol) * 2);

    float oacc[8][4];
    #pragma unroll
    for (int nt = 0; nt < 8; nt++)
        #pragma unroll
        for (int i = 0; i < 4; i++) oacc[nt][i] = 0.f;
    float mi[2] = { -INFINITY, -INFINITY };
    float li[2] = { 0.f, 0.f };

    const int NC = S_ / 64;
    for (int i = 0; i < NC; i++) {
        if (i + 1 < NC) CP_WAIT1(); else CP_WAIT0();
        __syncthreads();        // chunk i visible; all warps done chunk i-1
        if (i + 2 < NC) { load_kv(i + 2); CP_COMMIT(); }

        uint32_t kst = sb + (uint32_t)(i % NKV) * KV_STG;
        uint32_t vst = kst + VS_OFF;
        int kt = i * 64;

        // S = Q @ K^T  (K tile [j][d] = n-major -> native B frags)
        float sacc[8][4];
        #pragma unroll
        for (int nt = 0; nt < 8; nt++)
            #pragma unroll
            for (int j = 0; j < 4; j++) sacc[nt][j] = 0.f;
        #pragma unroll
        for (int ks = 0; ks < 4; ks++) {
            int kk = ks * 16;
            #pragma unroll
            for (int np = 0; np < 4; np++) {
                uint32_t bfr[4];
                ldsm_x4_u(bfr, kst + (np * 16 + kbr) * 144 + (kk + kbc) * 2);
                mma_bf16(sacc[2*np],     qa[ks], bfr[0], bfr[1]);
                mma_bf16(sacc[2*np + 1], qa[ks], bfr[2], bfr[3]);
            }
        }

        // mask (scores already in log2 domain; no scale multiply needed)
        #pragma unroll
        for (int nt = 0; nt < 8; nt++) {
            int jg = kt + nt * 8 + 2 * t;
            if (__ldg(mrow + jg)     == 0) { sacc[nt][0] = -1e9f; sacc[nt][2] = -1e9f; }
            if (__ldg(mrow + jg + 1) == 0) { sacc[nt][1] = -1e9f; sacc[nt][3] = -1e9f; }
        }

        // online softmax in log2 domain (rows g, g+8; stats across 4 t-lanes)
        #pragma unroll
        for (int h = 0; h < 2; h++) {
            float rm = -INFINITY;
            #pragma unroll
            for (int nt = 0; nt < 8; nt++)
                rm = fmaxf(rm, fmaxf(sacc[nt][2*h], sacc[nt][2*h + 1]));
            rm = fmaxf(rm, __shfl_xor_sync(0xffffffffu, rm, 1));
            rm = fmaxf(rm, __shfl_xor_sync(0xffffffffu, rm, 2));
            float mnew = fmaxf(mi[h], rm);
            float corr = ex2f(mi[h] - mnew);
            mi[h] = mnew;
            float rs = 0.f;
            #pragma unroll
            for (int nt = 0; nt < 8; nt++) {
                float e0 = ex2f(sacc[nt][2*h]     - mnew);
                float e1 = ex2f(sacc[nt][2*h + 1] - mnew);
                sacc[nt][2*h]     = e0;
                sacc[nt][2*h + 1] = e1;
                rs += e0 + e1;
            }
            rs += __shfl_xor_sync(0xffffffffu, rs, 1);
            rs += __shfl_xor_sync(0xffffffffu, rs, 2);
            li[h] = li[h] * corr + rs;
            #pragma unroll
            for (int nt = 0; nt < 8; nt++) {
                oacc[nt][2*h]     *= corr;
                oacc[nt][2*h + 1] *= corr;
            }
        }

        // O += P @ V. FA2 trick: S-accumulator layout == A-fragment layout,
        // so pack sacc pairs to bf16x2 and use directly (no P smem).
        #pragma unroll
        for (int js = 0; js < 4; js++) {
            uint32_t pa[4];
            pa[0] = packbf2(sacc[2*js    ][0], sacc[2*js    ][1]);
            pa[1] = packbf2(sacc[2*js    ][2], sacc[2*js    ][3]);
            pa[2] = packbf2(sacc[2*js + 1][0], sacc[2*js + 1][1]);
            pa[3] = packbf2(sacc[2*js + 1][2], sacc[2*js + 1][3]);
            int j0 = js * 16;
            #pragma unroll
            for (int np = 0; np < 4; np++) {
                uint32_t bfr[4];
                ldsm_x4_t_u(bfr, vst + (j0 + vbr) * 144 + (np * 16 + vbc) * 2);
                mma_bf16(oacc[2*np],     pa, bfr[0], bfr[1]);
                mma_bf16(oacc[2*np + 1], pa, bfr[2], bfr[3]);
            }
        }
    }

    // finalize: 1/l, write bf16 ctx in [B,S,E] layout
    #pragma unroll
    for (int h = 0; h < 2; h++) {
        float inv = 1.0f / li[h];
        int r = q0 + qb + g + 8 * h;
        __nv_bfloat16* orow = g_ctxb + ((size_t)bb * S_ + r) * E_ + hh * DH_;
        #pragma unroll
        for (int nt = 0; nt < 8; nt++) {
            int d = nt * 8 + 2 * t;
            *(__nv_bfloat162*)(orow + d) =
                __floats2bfloat162_rn(oacc[nt][2*h] * inv, oacc[nt][2*h + 1] * inv);
        }
    }
}

// ---------------------------------------------------------------------------
// kernel_launch: graph-capturable, no allocations
// ---------------------------------------------------------------------------
extern "C" void kernel_launch(void* const* d_in, const int* in_sizes, int n_in,
                              void* d_out, int out_size)
{
    const float* x    = (const float*)d_in[0];
    const int*   mask = (const int*)  d_in[1];
    const float* wq   = (const float*)d_in[2];
    const float* bq   = (const float*)d_in[3];
    const float* wk   = (const float*)d_in[4];
    const float* bk   = (const float*)d_in[5];
    const float* wv   = (const float*)d_in[6];
    const float* bv   = (const float*)d_in[7];
    const float* wo   = (const float*)d_in[8];
    const float* bo   = (const float*)d_in[9];
    const float* w1   = (const float*)d_in[10];
    const float* b1   = (const float*)d_in[11];
    const float* w2   = (const float*)d_in[12];
    const float* b2   = (const float*)d_in[13];
    const float* al1  = (const float*)d_in[14];
    const float* be1  = (const float*)d_in[15];
    const float* al2  = (const float*)d_in[16];
    const float* be2  = (const float*)d_in[17];
    float* out = (float*)d_out;

    cudaFuncSetAttribute(gemm_bf16<EpiQKV3>,
        cudaFuncAttributeMaxDynamicSharedMemorySize, GT_SMEM);
    cudaFuncSetAttribute(gemm_bf16<EpiOProj>,
        cudaFuncAttributeMaxDynamicSharedMemorySize, GT_SMEM);
    cudaFuncSetAttribute(gemm_bf16<EpiRelu>,
        cudaFuncAttributeMaxDynamicSharedMemorySize, GT_SMEM);
    cudaFuncSetAttribute(gemm_bf16<EpiFinal>,
        cudaFuncAttributeMaxDynamicSharedMemorySize, GT_SMEM);
    cudaFuncSetAttribute(attn_bf16,
        cudaFuncAttributeMaxDynamicSharedMemorySize, ATTN_SMEM);

    // all six weight transposes in ONE launch
    wtrans_all<<<3072, dim3(32, 8)>>>(wq, wk, wv, wo, w1, w2);

    // norm1
    ln_kernel<<<M_, 128>>>(x, al1, be1, 0);

    // Q/K/V projections (one launch, z selects weight/out)
    dim3 gqkv(E_ / 128, M_ / 128, 3);
    gemm_bf16<EpiQKV3><<<gqkv, 256, GT_SMEM>>>(
        0, 0, E_, E_, EpiQKV3{bq, bk, bv});

    // attention (128 queries per CTA)
    dim3 ga(S_ / 128, B_ * H_);
    attn_bf16<<<ga, 256, ATTN_SMEM>>>(mask);

    // O projection + residual 1
    dim3 g512(E_ / 128, M_ / 128, 1);
    gemm_bf16<EpiOProj><<<g512, 256, GT_SMEM>>>(
        1, 3, E_, E_, EpiOProj{bo, x});

    // norm2
    ln_kernel<<<M_, 128>>>(nullptr, al2, be2, 1);

    // FFN1 (N=2048) with ReLU
    dim3 gff1(FF2 / 128, M_ / 128, 1);
    gemm_bf16<EpiRelu><<<gff1, 256, GT_SMEM>>>(
        2, 4, E_, FF2, EpiRelu{b1});

    // FFN2 (K=2048) + residual 2 -> final output
    gemm_bf16<EpiFinal><<<g512, 256, GT_SMEM>>>(
        3, 5, FF2, E_, EpiFinal{out, b2});
}

// round 15
// speedup vs baseline: 1.1485x; 1.0109x over previous
#include <cuda_runtime.h>
#include <cuda_bf16.h>
#include <math.h>
#include <stdint.h>

// Problem dims (fixed by the reference)
#define B_   4
#define S_   2048
#define E_   512
#define H_   8
#define DH_  64
#define FF2  2048
#define M_   8192   // B_*S_

// ---------------------------------------------------------------------------
// Scratch buffers (device globals -- no allocations allowed)
// ---------------------------------------------------------------------------
static __device__ __nv_bfloat16 g_nb  [(size_t)M_ * E_];   // LN1 out
static __device__ __nv_bfloat16 g_qb  [(size_t)M_ * E_];   // [B,H,S,DH] (prescaled)
static __device__ __nv_bfloat16 g_kb  [(size_t)M_ * E_];
static __device__ __nv_bfloat16 g_vb  [(size_t)M_ * E_];
static __device__ __nv_bfloat16 g_ctxb[(size_t)M_ * E_];   // attn out [B,S,E]
static __device__ __nv_bfloat16 g_n2b [(size_t)M_ * E_];   // LN2 out
static __device__ __nv_bfloat16 g_hb  [(size_t)M_ * FF2];  // FFN hidden
static __device__ float         g_x1  [(size_t)M_ * E_];   // residual-1 (fp32)
// transposed bf16 weights, layout [N][K]
static __device__ __nv_bfloat16 g_wtq[E_ * E_];
static __device__ __nv_bfloat16 g_wtk[E_ * E_];
static __device__ __nv_bfloat16 g_wtv[E_ * E_];
static __device__ __nv_bfloat16 g_wto[E_ * E_];
static __device__ __nv_bfloat16 g_wt1[(size_t)FF2 * E_];   // [2048][512]
static __device__ __nv_bfloat16 g_wt2[(size_t)E_ * FF2];   // [512][2048]
// mask bitwords: one uint64 per (batch, 64-key chunk)
static __device__ unsigned long long g_mbits[B_ * (S_ / 64)];

// 0.125 * log2(e): folded into Q so QK scores land in log2 domain
#define QSCALE 0.18033688011112042f

// ---------------------------------------------------------------------------
// PTX helpers (family-portable only: cp.async, ldmatrix, mma.sync)
// ---------------------------------------------------------------------------
__device__ __forceinline__ uint32_t smem_u32(const void* p) {
    return (uint32_t)__cvta_generic_to_shared(p);
}
__device__ __forceinline__ void cp_async16_s(uint32_t saddr, const void* g) {
    asm volatile("cp.async.cg.shared.global [%0], [%1], 16;"
                 :: "r"(saddr), "l"(g));
}
#define CP_COMMIT() asm volatile("cp.async.commit_group;" ::: "memory")
#define CP_WAIT0()  asm volatile("cp.async.wait_group 0;" ::: "memory")
#define CP_WAIT1()  asm volatile("cp.async.wait_group 1;" ::: "memory")
#define CP_WAIT2()  asm volatile("cp.async.wait_group 2;" ::: "memory")

__device__ __forceinline__ float ex2f(float x) {
    float r;
    asm("ex2.approx.ftz.f32 %0, %1;" : "=f"(r) : "f"(x));
    return r;
}

// bf16 m16n8k16 mma.sync
__device__ __forceinline__ void mma_bf16(float c[4], const uint32_t a[4],
                                         uint32_t b0, uint32_t b1)
{
    asm volatile(
        "mma.sync.aligned.m16n8k16.row.col.f32.bf16.bf16.f32 "
        "{%0,%1,%2,%3}, {%4,%5,%6,%7}, {%8,%9}, {%0,%1,%2,%3};"
        : "+f"(c[0]), "+f"(c[1]), "+f"(c[2]), "+f"(c[3])
        : "r"(a[0]), "r"(a[1]), "r"(a[2]), "r"(a[3]), "r"(b0), "r"(b1));
}
__device__ __forceinline__ void ldsm_x4_u(uint32_t r[4], uint32_t saddr) {
    asm volatile("ldmatrix.sync.aligned.m8n8.x4.shared.b16 {%0,%1,%2,%3}, [%4];"
        : "=r"(r[0]), "=r"(r[1]), "=r"(r[2]), "=r"(r[3]) : "r"(saddr));
}
__device__ __forceinline__ void ldsm_x4_t_u(uint32_t r[4], uint32_t saddr) {
    asm volatile("ldmatrix.sync.aligned.m8n8.x4.trans.shared.b16 {%0,%1,%2,%3}, [%4];"
        : "=r"(r[0]), "=r"(r[1]), "=r"(r[2]), "=r"(r[3]) : "r"(saddr));
}
__device__ __forceinline__ uint32_t packbf2(float a, float b) {
    __nv_bfloat162 v = __floats2bfloat162_rn(a, b);
    return *(uint32_t*)&v;
}

// ---------------------------------------------------------------------------
// Prep kernel (ONE launch, 128 threads/block):
//   blocks [0, 8192)          : LayerNorm-1 row (x -> g_nb, bf16)
//   blocks [8192, 11264)      : weight transpose tiles fp32 [K,N] -> bf16 [N,K]
//   block  11264              : mask -> 64-bit words g_mbits
// ---------------------------------------------------------------------------
__global__ void prep_kernel(const float* __restrict__ x,
                            const float* __restrict__ alpha,
                            const float* __restrict__ beta,
                            const int* __restrict__ mask,
                            const float* __restrict__ wq, const float* __restrict__ wk,
                            const float* __restrict__ wv, const float* __restrict__ wo,
                            const float* __restrict__ w1, const float* __restrict__ w2)
{
    int bid = blockIdx.x;
    int tid = threadIdx.x;

    if (bid < M_) {
        // ---- LayerNorm row (mean + unbiased std ddof=1, eps on std) ----
        int row = bid;
        float4 v = ((const float4*)(x + (size_t)row * E_))[tid];
        float s  = v.x + v.y + v.z + v.w;
        float sq = v.x*v.x + v.y*v.y + v.z*v.z + v.w*v.w;
        #pragma unroll
        for (int o = 16; o; o >>= 1) {
            s  += __shfl_xor_sync(0xffffffffu, s,  o);
            sq += __shfl_xor_sync(0xffffffffu, sq, o);
        }
        __shared__ float ss[4], sqs[4];
        int w = tid >> 5;
        if ((tid & 31) == 0) { ss[w] = s; sqs[w] = sq; }
        __syncthreads();
        s  = ss[0] + ss[1] + ss[2] + ss[3];
        sq = sqs[0] + sqs[1] + sqs[2] + sqs[3];
        float mean = s * (1.0f / E_);
        float var  = fmaxf((sq - (float)E_ * mean * mean) * (1.0f / (E_ - 1)), 0.0f);
        float scal = alpha[0] / (sqrtf(var) + 1e-6f);
        float b    = beta[0];
        __nv_bfloat162 o0 = __floats2bfloat162_rn((v.x - mean) * scal + b,
                                                  (v.y - mean) * scal + b);
        __nv_bfloat162 o1 = __floats2bfloat162_rn((v.z - mean) * scal + b,
                                                  (v.w - mean) * scal + b);
        uint2 pk = make_uint2(*(uint32_t*)&o0, *(uint32_t*)&o1);
        ((uint2*)(g_nb + (size_t)row * E_))[tid] = pk;
    } else if (bid < M_ + 3072) {
        // ---- weight transpose tile ----
        int wb = bid - M_;
        const float* in; __nv_bfloat16* out; int K, N, tile;
        if (wb < 1024) {
            int w = wb >> 8; tile = wb & 255; K = E_; N = E_;
            in  = (w == 0) ? wq : (w == 1) ? wk : (w == 2) ? wv : wo;
            out = (w == 0) ? g_wtq : (w == 1) ? g_wtk : (w == 2) ? g_wtv : g_wto;
        } else if (wb < 2048) {
            tile = wb - 1024; K = E_; N = FF2; in = w1; out = g_wt1;
        } else {
            tile = wb - 2048; K = FF2; N = E_; in = w2; out = g_wt2;
        }
        int tilesX = N >> 5;
        int bx = (tile % tilesX) << 5, by = (tile / tilesX) << 5;
        __shared__ float t[32][33];
        int tx = tid & 31, ty = tid >> 5;            // 32 x 4
        #pragma unroll
        for (int j = 0; j < 32; j += 4)
            t[ty + j][tx] = in[(size_t)(by + ty + j) * N + bx + tx];
        __syncthreads();
        #pragma unroll
        for (int j = 0; j < 32; j += 4)
            out[(size_t)(bx + ty + j) * K + by + tx] =
                __float2bfloat16(t[tx][ty + j]);
    } else {
        // ---- mask bitwords: word w covers batch w>>5, keys [(w&31)*64, +64) ----
        int w = tid;                                  // 128 words total
        int b = w >> 5, c = w & 31;
        const int* mp = mask + b * S_ + c * 64;
        unsigned long long bits = 0ull;
        #pragma unroll
        for (int k = 0; k < 64; k++)
            bits |= (unsigned long long)(mp[k] != 0) << k;
        g_mbits[w] = bits;
    }
}

// ---------------------------------------------------------------------------
// LayerNorm-2 (g_x1 -> g_n2b)
// ---------------------------------------------------------------------------
__global__ void ln2_kernel(const float* __restrict__ alpha,
                           const float* __restrict__ beta)
{
    int row = blockIdx.x;
    int t   = threadIdx.x;
    float4 v = ((const float4*)(g_x1 + (size_t)row * E_))[t];
    float s  = v.x + v.y + v.z + v.w;
    float sq = v.x*v.x + v.y*v.y + v.z*v.z + v.w*v.w;
    #pragma unroll
    for (int o = 16; o; o >>= 1) {
        s  += __shfl_xor_sync(0xffffffffu, s,  o);
        sq += __shfl_xor_sync(0xffffffffu, sq, o);
    }
    __shared__ float ss[4], sqs[4];
    int w = t >> 5;
    if ((t & 31) == 0) { ss[w] = s; sqs[w] = sq; }
    __syncthreads();
    s  = ss[0] + ss[1] + ss[2] + ss[3];
    sq = sqs[0] + sqs[1] + sqs[2] + sqs[3];
    float mean = s * (1.0f / E_);
    float var  = fmaxf((sq - (float)E_ * mean * mean) * (1.0f / (E_ - 1)), 0.0f);
    float scal = alpha[0] / (sqrtf(var) + 1e-6f);
    float b    = beta[0];
    __nv_bfloat162 o0 = __floats2bfloat162_rn((v.x - mean) * scal + b,
                                              (v.y - mean) * scal + b);
    __nv_bfloat162 o1 = __floats2bfloat162_rn((v.z - mean) * scal + b,
                                              (v.w - mean) * scal + b);
    uint2 pk = make_uint2(*(uint32_t*)&o0, *(uint32_t*)&o1);
    ((uint2*)(g_n2b + (size_t)row * E_))[t] = pk;
}

// ---------------------------------------------------------------------------
// Epilogue functors: (m, n, v0, v1) = two adjacent-n fp32 accumulator values
// ---------------------------------------------------------------------------
struct EpiQKV3 {                // z selects q/k/v; bf16 out in [B,H,S,DH]
    const float *bq, *bk, *bv;  // Q is prescaled by QSCALE (log2-domain scores)
    __device__ __forceinline__ void operator()(int m, int n, float v0, float v1) const {
        int z = blockIdx.z;
        const float* bias  = (z == 0) ? bq : (z == 1) ? bk : bv;
        __nv_bfloat16* out = (z == 0) ? g_qb : (z == 1) ? g_kb : g_vb;
        float sc = (z == 0) ? QSCALE : 1.0f;
        int b = m >> 11, s = m & (S_ - 1);
        int h = n >> 6,  d = n & 63;
        __nv_bfloat162 o = __floats2bfloat162_rn((v0 + bias[n]) * sc,
                                                 (v1 + bias[n + 1]) * sc);
        *(__nv_bfloat162*)(out + ((((size_t)b * H_ + h) * S_ + s) * DH_ + d)) = o;
    }
};
struct EpiOProj {               // g_x1 = x + ctx@wo + bo   (fp32)
    const float* bias; const float* resid;
    __device__ __forceinline__ void operator()(int m, int n, float v0, float v1) const {
        size_t idx = (size_t)m * E_ + n;
        float2 r = *(const float2*)(resid + idx);
        *(float2*)(g_x1 + idx) =
            make_float2(v0 + bias[n] + r.x, v1 + bias[n + 1] + r.y);
    }
};
struct EpiRelu {                // g_hb = relu(n2@w1 + b1)  (bf16)
    const float* bias;
    __device__ __forceinline__ void operator()(int m, int n, float v0, float v1) const {
        __nv_bfloat162 o = __floats2bfloat162_rn(fmaxf(v0 + bias[n],     0.f),
                                                 fmaxf(v1 + bias[n + 1], 0.f));
        *(__nv_bfloat162*)(g_hb + (size_t)m * FF2 + n) = o;
    }
};
struct EpiFinal {               // out = x1 + h@w2 + b2     (fp32)
    float* out; const float* bias;
    __device__ __forceinline__ void operator()(int m, int n, float v0, float v1) const {
        size_t idx = (size_t)m * E_ + n;
        float2 r = *(const float2*)(g_x1 + idx);
        *(float2*)(out + idx) =
            make_float2(v0 + bias[n] + r.x, v1 + bias[n + 1] + r.y);
    }
};

__device__ __forceinline__ const __nv_bfloat16* gemm_A(int s) {
    return (s == 0) ? g_nb : (s == 1) ? g_ctxb : (s == 2) ? g_n2b : g_hb;
}
__device__ __forceinline__ const __nv_bfloat16* gemm_W(int s) {
    return (s == 0) ? g_wtq : (s == 1) ? g_wtk : (s == 2) ? g_wtv
         : (s == 3) ? g_wto : (s == 4) ? g_wt1 : g_wt2;
}

// ---------------------------------------------------------------------------
// bf16 mma.sync GEMM: C[M,N] = A[M,K] @ Wt[N,K]^T  (+ epilogue)
// CTA tile 128x128, BK=64, 256 threads = 8 warps (4m x 2n), warp tile 32x64.
// 3-stage cp.async ring, ONE __syncthreads per chunk.
// Row stride 144 B: (9r+c) mod 8 permutation -> ldmatrix conflict-free.
// ---------------------------------------------------------------------------
#define G_ROWB       144
#define GA_BYTES     (128 * G_ROWB)          // 18432
#define GSTAGE_BYTES (2 * GA_BYTES)          // 36864
#define GT_SMEM      (3 * GSTAGE_BYTES)      // 110592

template <class Epi>
__global__ void __launch_bounds__(256, 2)
gemm_bf16(int asel, int wsel0, int K, int N, Epi epi)
{
    extern __shared__ char smem[];
    uint32_t sb = smem_u32(smem);
    const __nv_bfloat16* A = gemm_A(asel);
    const __nv_bfloat16* W = gemm_W(wsel0 + blockIdx.z);
    int m0 = blockIdx.y * 128, n0 = blockIdx.x * 128;
    int tid = threadIdx.x, wid = tid >> 5, lane = tid & 31;
    int g = lane >> 2, t = lane & 3;
    int wm = wid & 3, wn = wid >> 2;
    // ldmatrix lane offsets
    int arow = lane & 15;                        // A: rows 0..15
    int acol = (lane >> 4) << 3;                 // A: k halves
    int brow = ((lane >> 4) << 3) + (lane & 7);  // B: n offset 0..15
    int bcol = ((lane >> 3) & 1) << 3;           // B: k halves

    const __nv_bfloat16* Ab = A + (size_t)m0 * K;
    const __nv_bfloat16* Wb = W + (size_t)n0 * K;
    const int NC = K >> 6;                       // BK=64 chunks

    auto load_chunk = [&](int ci) {
        uint32_t base = sb + (uint32_t)(ci % 3) * GSTAGE_BYTES;
        const __nv_bfloat16* Ap = Ab + ci * 64;
        const __nv_bfloat16* Wp = Wb + ci * 64;
        #pragma unroll
        for (int i = 0; i < 4; i++) {            // 1024 16B-groups / 256 thr
            int idx = tid + i * 256;
            int r = idx >> 3, cg = idx & 7;
            cp_async16_s(base + r * G_ROWB + cg * 16,
                         Ap + (size_t)r * K + cg * 8);
            cp_async16_s(base + GA_BYTES + r * G_ROWB + cg * 16,
                         Wp + (size_t)r * K + cg * 8);
        }
    };

    float acc[2][8][4];
    #pragma unroll
    for (int mt = 0; mt < 2; mt++)
        #pragma unroll
        for (int nt = 0; nt < 8; nt++)
            #pragma unroll
            for (int i = 0; i < 4; i++) acc[mt][nt][i] = 0.f;

    load_chunk(0); CP_COMMIT();
    if (NC > 1) { load_chunk(1); CP_COMMIT(); }

    for (int i = 0; i < NC; i++) {
        if (i + 1 < NC) CP_WAIT1(); else CP_WAIT0();
        __syncthreads();                 // chunk i visible; all done chunk i-1
        if (i + 2 < NC) { load_chunk(i + 2); CP_COMMIT(); }

        uint32_t abase = sb + (uint32_t)(i % 3) * GSTAGE_BYTES;
        uint32_t bbase = abase + GA_BYTES;
        #pragma unroll
        for (int ks = 0; ks < 4; ks++) {
            int kk = ks * 16;
            uint32_t a[2][4];
            #pragma unroll
            for (int mt = 0; mt < 2; mt++)
                ldsm_x4_u(a[mt], abase + (wm * 32 + mt * 16 + arow) * G_ROWB
                                        + (kk + acol) * 2);
            #pragma unroll
            for (int np = 0; np < 4; np++) {
                uint32_t bfr[4];
                ldsm_x4_u(bfr, bbase + (wn * 64 + np * 16 + brow) * G_ROWB
                                      + (kk + bcol) * 2);
                #pragma unroll
                for (int mt = 0; mt < 2; mt++) {
                    mma_bf16(acc[mt][2*np],     a[mt], bfr[0], bfr[1]);
                    mma_bf16(acc[mt][2*np + 1], a[mt], bfr[2], bfr[3]);
                }
            }
        }
    }

    #pragma unroll
    for (int mt = 0; mt < 2; mt++) {
        int rb = m0 + wm * 32 + mt * 16;
        #pragma unroll
        for (int nt = 0; nt < 8; nt++) {
            int n = n0 + wn * 64 + nt * 8 + 2 * t;
            epi(rb + g,     n, acc[mt][nt][0], acc[mt][nt][1]);
            epi(rb + g + 8, n, acc[mt][nt][2], acc[mt][nt][3]);
        }
    }
}

// ---------------------------------------------------------------------------
// Flash attention, bf16 m16n8k16 mma.sync, FA2 register-P.
// One CTA = 128 queries of one (b,h), 256 threads = 8 warps.
// 64-key chunks in a 4-stage cp.async ring processed in PAIRS: one barrier
// window covers two chunks, letting warps de-phase across softmax/MMA phases
// (breaks the per-chunk convoy). Mask applied via precomputed bitwords with a
// uniform all-ones fast path. Scores in log2 domain; ex2.approx softmax.
// smem rows stride 144 B: Ks[4][64], Vs[4][64], Qs[128].
// ---------------------------------------------------------------------------
#define NKV       4
#define KV_STG    (64 * 144)              // 9216
#define VS_OFF    (NKV * KV_STG)          // 36864
#define QS_OFF    (2 * NKV * KV_STG)      // 73728
#define ATTN_SMEM (QS_OFF + 128 * 144)    // 92160

__global__ void __launch_bounds__(256, 2)
attn_bf16(const int* __restrict__ mask)
{
    extern __shared__ char smem[];
    uint32_t sb = smem_u32(smem);

    int tid  = threadIdx.x;
    int wid  = tid >> 5, lane = tid & 31;
    int g    = lane >> 2, t = lane & 3;
    int qb   = wid * 16;
    // ldmatrix lane offsets
    int arow = lane & 15;                  // A frag row
    int acol = (lane >> 4) << 3;           // A frag col (elems)
    int kbr  = ((lane >> 4) << 3) + (lane & 7);        // K B-frag: n offset
    int kbc  = ((lane >> 3) & 1) << 3;                 // K B-frag: k offset
    int vbr  = (((lane >> 3) & 1) << 3) + (lane & 7);  // V trans: j offset
    int vbc  = (lane >> 4) << 3;                       // V trans: d offset

    int bh = blockIdx.y;
    int q0 = blockIdx.x * 128;
    int bb = bh >> 3, hh = bh & 7;
    const __nv_bfloat16* Qb = g_qb + (size_t)bh * S_ * DH_;
    const __nv_bfloat16* Kb = g_kb + (size_t)bh * S_ * DH_;
    const __nv_bfloat16* Vb = g_vb + (size_t)bh * S_ * DH_;
    const unsigned long long* mbits = g_mbits + bb * (S_ / 64);

    auto load_kv = [&](int ci) {
        uint32_t st = (uint32_t)(ci & 3) * KV_STG;
        #pragma unroll
        for (int i = 0; i < 2; i++) {               // 512 16B-chunks / 256 thr
            int idx = tid + i * 256;
            int r = idx >> 3, cB = (idx & 7) << 4;
            cp_async16_s(sb + st + r * 144 + cB,
                         Kb + (size_t)(ci * 64 + r) * DH_ + (cB >> 1));
            cp_async16_s(sb + VS_OFF + st + r * 144 + cB,
                         Vb + (size_t)(ci * 64 + r) * DH_ + (cB >> 1));
        }
    };

    // stage Q (prescaled in projection) into Qs (128 rows)
    #pragma unroll
    for (int i = 0; i < 4; i++) {
        int idx = tid + i * 256;
        int r = idx >> 3, cB = (idx & 7) << 4;
        cp_async16_s(sb + QS_OFF + r * 144 + cB,
                     Qb + (size_t)(q0 + r) * DH_ + (cB >> 1));
    }
    CP_COMMIT();
    load_kv(0); load_kv(1); CP_COMMIT();   // pair 0
    load_kv(2); load_kv(3); CP_COMMIT();   // pair 1

    CP_WAIT2();                 // Q resident (2 pair-groups outstanding)
    __syncthreads();
    uint32_t qa[4][4];
    #pragma unroll
    for (int ks = 0; ks < 4; ks++)
        ldsm_x4_u(qa[ks], sb + QS_OFF + (qb + arow) * 144 + (ks * 16 + acol) * 2);

    float oacc[8][4];
    #pragma unroll
    for (int nt = 0; nt < 8; nt++)
        #pragma unroll
        for (int i = 0; i < 4; i++) oacc[nt][i] = 0.f;
    float mi[2] = { -INFINITY, -INFINITY };
    float li[2] = { 0.f, 0.f };

    // -------- one 64-key chunk: QK, mask, online softmax, PV --------
    auto do_chunk = [&](int c) {
        uint32_t kst = sb + (uint32_t)(c & 3) * KV_STG;
        uint32_t vst = kst + VS_OFF;

        // S = Q @ K^T  (K tile [j][d] = n-major -> native B frags)
        float sacc[8][4];
        #pragma unroll
        for (int nt = 0; nt < 8; nt++)
            #pragma unroll
            for (int j = 0; j < 4; j++) sacc[nt][j] = 0.f;
        #pragma unroll
        for (int ks = 0; ks < 4; ks++) {
            int kk = ks * 16;
            #pragma unroll
            for (int np = 0; np < 4; np++) {
                uint32_t bfr[4];
                ldsm_x4_u(bfr, kst + (np * 16 + kbr) * 144 + (kk + kbc) * 2);
                mma_bf16(sacc[2*np],     qa[ks], bfr[0], bfr[1]);
                mma_bf16(sacc[2*np + 1], qa[ks], bfr[2], bfr[3]);
            }
        }

        // mask via bitword; uniform fast path when all keys valid
        unsigned long long bits = mbits[c];
        if (bits != 0xFFFFFFFFFFFFFFFFull) {
            #pragma unroll
            for (int nt = 0; nt < 8; nt++) {
                int jb = nt * 8 + 2 * t;
                if (!((bits >> jb) & 1))       { sacc[nt][0] = -1e9f; sacc[nt][2] = -1e9f; }
                if (!((bits >> (jb + 1)) & 1)) { sacc[nt][1] = -1e9f; sacc[nt][3] = -1e9f; }
            }
        }

        // online softmax in log2 domain (rows g, g+8; stats across 4 t-lanes)
        #pragma unroll
        for (int h = 0; h < 2; h++) {
            float rm = -INFINITY;
            #pragma unroll
            for (int nt = 0; nt < 8; nt++)
                rm = fmaxf(rm, fmaxf(sacc[nt][2*h], sacc[nt][2*h + 1]));
            rm = fmaxf(rm, __shfl_xor_sync(0xffffffffu, rm, 1));
            rm = fmaxf(rm, __shfl_xor_sync(0xffffffffu, rm, 2));
            float mnew = fmaxf(mi[h], rm);
            float corr = ex2f(mi[h] - mnew);
            mi[h] = mnew;
            float rs = 0.f;
            #pragma unroll
            for (int nt = 0; nt < 8; nt++) {
                float e0 = ex2f(sacc[nt][2*h]     - mnew);
                float e1 = ex2f(sacc[nt][2*h + 1] - mnew);
                sacc[nt][2*h]     = e0;
                sacc[nt][2*h + 1] = e1;
                rs += e0 + e1;
            }
            rs += __shfl_xor_sync(0xffffffffu, rs, 1);
            rs += __shfl_xor_sync(0xffffffffu, rs, 2);
            li[h] = li[h] * corr + rs;
            #pragma unroll
            for (int nt = 0; nt < 8; nt++) {
                oacc[nt][2*h]     *= corr;
                oacc[nt][2*h + 1] *= corr;
            }
        }

        // O += P @ V  (register-P: S-accumulator layout == A-fragment layout)
        #pragma unroll
        for (int js = 0; js < 4; js++) {
            uint32_t pa[4];
            pa[0] = packbf2(sacc[2*js    ][0], sacc[2*js    ][1]);
            pa[1] = packbf2(sacc[2*js    ][2], sacc[2*js    ][3]);
            pa[2] = packbf2(sacc[2*js + 1][0], sacc[2*js + 1][1]);
            pa[3] = packbf2(sacc[2*js + 1][2], sacc[2*js + 1][3]);
            int j0 = js * 16;
            #pragma unroll
            for (int np = 0; np < 4; np++) {
                uint32_t bfr[4];
                ldsm_x4_t_u(bfr, vst + (j0 + vbr) * 144 + (np * 16 + vbc) * 2);
                mma_bf16(oacc[2*np],     pa, bfr[0], bfr[1]);
                mma_bf16(oacc[2*np + 1], pa, bfr[2], bfr[3]);
            }
        }
    };

    const int NP = S_ / 128;                 // 16 chunk-pairs
    for (int p = 0; p < NP; p++) {
        if (p + 1 < NP) CP_WAIT1(); else CP_WAIT0();
        __syncthreads();                     // pair p visible to all warps
        do_chunk(2 * p);
        do_chunk(2 * p + 1);
        __syncthreads();                     // all warps done pair p's stages
        if (p + 2 < NP) {
            load_kv(2 * p + 4); load_kv(2 * p + 5); CP_COMMIT();
        }
    }

    // finalize: 1/l, write bf16 ctx in [B,S,E] layout
    #pragma unroll
    for (int h = 0; h < 2; h++) {
        float inv = 1.0f / li[h];
        int r = q0 + qb + g + 8 * h;
        __nv_bfloat16* orow = g_ctxb + ((size_t)bb * S_ + r) * E_ + hh * DH_;
        #pragma unroll
        for (int nt = 0; nt < 8; nt++) {
            int d = nt * 8 + 2 * t;
            *(__nv_bfloat162*)(orow + d) =
                __floats2bfloat162_rn(oacc[nt][2*h] * inv, oacc[nt][2*h + 1] * inv);
        }
    }
}

// ---------------------------------------------------------------------------
// kernel_launch: graph-capturable, no allocations
// ---------------------------------------------------------------------------
extern "C" void kernel_launch(void* const* d_in, const int* in_sizes, int n_in,
                              void* d_out, int out_size)
{
    const float* x    = (const float*)d_in[0];
    const int*   mask = (const int*)  d_in[1];
    const float* wq   = (const float*)d_in[2];
    const float* bq   = (const float*)d_in[3];
    const float* wk   = (const float*)d_in[4];
    const float* bk   = (const float*)d_in[5];
    const float* wv   = (const float*)d_in[6];
    const float* bv   = (const float*)d_in[7];
    const float* wo   = (const float*)d_in[8];
    const float* bo   = (const float*)d_in[9];
    const float* w1   = (const float*)d_in[10];
    const float* b1   = (const float*)d_in[11];
    const float* w2   = (const float*)d_in[12];
    const float* b2   = (const float*)d_in[13];
    const float* al1  = (const float*)d_in[14];
    const float* be1  = (const float*)d_in[15];
    const float* al2  = (const float*)d_in[16];
    const float* be2  = (const float*)d_in[17];
    float* out = (float*)d_out;

    cudaFuncSetAttribute(gemm_bf16<EpiQKV3>,
        cudaFuncAttributeMaxDynamicSharedMemorySize, GT_SMEM);
    cudaFuncSetAttribute(gemm_bf16<EpiOProj>,
        cudaFuncAttributeMaxDynamicSharedMemorySize, GT_SMEM);
    cudaFuncSetAttribute(gemm_bf16<EpiRelu>,
        cudaFuncAttributeMaxDynamicSharedMemorySize, GT_SMEM);
    cudaFuncSetAttribute(gemm_bf16<EpiFinal>,
        cudaFuncAttributeMaxDynamicSharedMemorySize, GT_SMEM);
    cudaFuncSetAttribute(attn_bf16,
        cudaFuncAttributeMaxDynamicSharedMemorySize, ATTN_SMEM);

    // LN1 + all six weight transposes + mask bitwords in ONE launch
    prep_kernel<<<M_ + 3072 + 1, 128>>>(x, al1, be1, mask,
                                        wq, wk, wv, wo, w1, w2);

    // Q/K/V projections (one launch, z selects weight/out)
    dim3 gqkv(E_ / 128, M_ / 128, 3);
    gemm_bf16<EpiQKV3><<<gqkv, 256, GT_SMEM>>>(
        0, 0, E_, E_, EpiQKV3{bq, bk, bv});

    // attention (128 queries per CTA)
    dim3 ga(S_ / 128, B_ * H_);
    attn_bf16<<<ga, 256, ATTN_SMEM>>>(mask);

    // O projection + residual 1
    dim3 g512(E_ / 128, M_ / 128, 1);
    gemm_bf16<EpiOProj><<<g512, 256, GT_SMEM>>>(
        1, 3, E_, E_, EpiOProj{bo, x});

    // norm2
    ln2_kernel<<<M_, 128>>>(al2, be2);

    // FFN1 (N=2048) with ReLU
    dim3 gff1(FF2 / 128, M_ / 128, 1);
    gemm_bf16<EpiRelu><<<gff1, 256, GT_SMEM>>>(
        2, 4, E_, FF2, EpiRelu{b1});

    // FFN2 (K=2048) + residual 2 -> final output
    gemm_bf16<EpiFinal><<<g512, 256, GT_SMEM>>>(
        3, 5, FF2, E_, EpiFinal{out, b2});
}